// round 2
// baseline (speedup 1.0000x reference)
#include <cuda_runtime.h>

// ---------------------------------------------------------------------------
// WindowAttention fused kernel (fp32, packed f32x2 FFMA), sm_103a
//   B_=2048 windows, N=64 tokens, DIM=128, H=8, HD=16
// ---------------------------------------------------------------------------

#define NWIN   2048
#define NW_PER 1024
#define NTOK   64
#define DIM    128
#define NHEAD  8
#define HD     16
#define ATT_SCALE 0.25f   // 16^-0.5

typedef unsigned long long u64;

// device scratch (no cudaMalloc allowed)
__device__ float g_rpb[NHEAD * NTOK * NTOK];   // [h][n][m]
__device__ float g_aff[512];                   // [b][scale(128)|bias(128)]

// ---- packed f32x2 helpers -------------------------------------------------
__device__ __forceinline__ u64 pack2(float lo, float hi) {
    u64 r; asm("mov.b64 %0, {%1,%2};" : "=l"(r) : "f"(lo), "f"(hi)); return r;
}
__device__ __forceinline__ float2 unpack2(u64 v) {
    float2 f; asm("mov.b64 {%0,%1}, %2;" : "=f"(f.x), "=f"(f.y) : "l"(v)); return f;
}
__device__ __forceinline__ void ffma2(u64& d, u64 a, u64 b) {
    asm("fma.rn.f32x2 %0, %1, %2, %3;" : "=l"(d) : "l"(a), "l"(b), "l"(d));
}

// ---- prep: rel-pos-bias gather + affine MLP -------------------------------
__global__ void prep_kernel(const float* __restrict__ frame_type,
                            const float* __restrict__ table,
                            const float* __restrict__ aff_w1,
                            const float* __restrict__ aff_b1,
                            const float* __restrict__ aff_w2,
                            const int*   __restrict__ rel_index) {
    int tid = threadIdx.x;
    int blk = blockIdx.x;
    if (blk < 128) {
        int idx = blk * 256 + tid;               // < 32768
        int h  = idx >> 12;
        int nm = idx & 4095;
        g_rpb[idx] = table[rel_index[nm] * NHEAD + h];
    } else {
        int c = tid;                             // 0..255
        for (int b = 0; b < 2; b++) {
            float hdn[16];
#pragma unroll
            for (int j = 0; j < 16; j++) {
                float a = aff_b1[j];
                a = fmaf(frame_type[b * 2 + 0], aff_w1[j * 2 + 0], a);
                a = fmaf(frame_type[b * 2 + 1], aff_w1[j * 2 + 1], a);
                hdn[j] = 1.f / (1.f + __expf(-a));
            }
            float ap = 0.f;
#pragma unroll
            for (int j = 0; j < 16; j++) ap = fmaf(hdn[j], aff_w2[c * 16 + j], ap);
            if (c < 128) {
                // softplus(ap), numerically stable
                g_aff[b * 256 + c] = fmaxf(ap, 0.f) + log1pf(__expf(-fabsf(ap)));
            } else {
                g_aff[b * 256 + c] = ap;         // bias as-is
            }
        }
    }
}

// ---- SMEM layout (floats) -------------------------------------------------
#define SM_X   0        // 64x128 input tile, reused as attention-out tile
#define SM_Q   8192     // [h][n][d]  8*64*16
#define SM_K   16384
#define SM_V   24576
#define SM_W   32768    // qkv-phase W chunk: WcT[32][386]
#define WSTR   386
#define SMEM_FLOATS (32768 + 32 * WSTR)          // 45120
#define SMEM_BYTES  (SMEM_FLOATS * 4)            // 180480
#define PSTR   130                                // proj-phase PwT stride (at SM_Q)

// ---- main fused kernel ----------------------------------------------------
__global__ __launch_bounds__(256, 1)
void win_attn_kernel(const float* __restrict__ x,
                     const float* __restrict__ mask,
                     const float* __restrict__ qkv_w,
                     const float* __restrict__ qkv_b,
                     const float* __restrict__ proj_w,
                     const float* __restrict__ proj_b,
                     float* __restrict__ out) {
    extern __shared__ float smem[];
    const int tid  = threadIdx.x;
    const int bwin = blockIdx.x;
    const int bat  = bwin >> 10;        // true batch (0/1)
    const int w    = bwin & 1023;       // window index for mask
    const int tx   = tid & 15;
    const int ty   = tid >> 4;

    // ---- load x tile (64x128) -------------------------------------------
    {
        const float4* xg4 = (const float4*)(x + (size_t)bwin * NTOK * DIM);
        float4* xs4 = (float4*)(smem + SM_X);
        for (int i = tid; i < NTOK * DIM / 4; i += 256) xs4[i] = xg4[i];
    }
    __syncthreads();

    // ---- phase 1: QKV GEMM 64x384x128 (f32x2) ---------------------------
    u64 acc[4][12];
#pragma unroll
    for (int ri = 0; ri < 4; ri++)
#pragma unroll
        for (int ci = 0; ci < 12; ci++) acc[ri][ci] = 0ULL;

    float* WcT = smem + SM_W;
    for (int kc = 0; kc < 4; kc++) {
        const int k0 = kc * 32;
        if (kc) __syncthreads();   // previous chunk fully consumed
        // stage W chunk: WcT[j][co] = qkv_w[co][k0+j], float4 global loads
        for (int i4 = tid; i4 < 384 * 8; i4 += 256) {
            int co = i4 >> 3, j4 = i4 & 7;
            float4 v = *(const float4*)(qkv_w + co * DIM + k0 + j4 * 4);
            WcT[(j4 * 4 + 0) * WSTR + co] = v.x;
            WcT[(j4 * 4 + 1) * WSTR + co] = v.y;
            WcT[(j4 * 4 + 2) * WSTR + co] = v.z;
            WcT[(j4 * 4 + 3) * WSTR + co] = v.w;
        }
        __syncthreads();
#pragma unroll 8
        for (int j = 0; j < 32; j++) {
            const float* wr = WcT + j * WSTR + 2 * tx;
            u64 xx[4];
#pragma unroll
            for (int ri = 0; ri < 4; ri++) {
                float xv = smem[SM_X + (ty + 16 * ri) * DIM + k0 + j];
                xx[ri] = pack2(xv, xv);
            }
#pragma unroll
            for (int ci = 0; ci < 12; ci++) {
                u64 w2 = *(const u64*)(wr + 32 * ci);
#pragma unroll
                for (int ri = 0; ri < 4; ri++) ffma2(acc[ri][ci], xx[ri], w2);
            }
        }
    }
    __syncthreads();

    // ---- writeback q (scaled), k, v (affine) into [h][n][d] SMEM --------
#pragma unroll
    for (int ci = 0; ci < 12; ci++) {
        const int co0 = 32 * ci + 2 * tx;        // even
        const float2 bb = make_float2(qkv_b[co0], qkv_b[co0 + 1]);
        if (ci < 4) {
            const int h = co0 >> 4, d = co0 & 15;
#pragma unroll
            for (int ri = 0; ri < 4; ri++) {
                const int n = ty + 16 * ri;
                float2 v2 = unpack2(acc[ri][ci]);
                smem[SM_Q + h * 1024 + n * 16 + d]     = (v2.x + bb.x) * ATT_SCALE;
                smem[SM_Q + h * 1024 + n * 16 + d + 1] = (v2.y + bb.y) * ATT_SCALE;
            }
        } else if (ci < 8) {
            const int c = co0 - 128, h = c >> 4, d = c & 15;
#pragma unroll
            for (int ri = 0; ri < 4; ri++) {
                const int n = ty + 16 * ri;
                float2 v2 = unpack2(acc[ri][ci]);
                smem[SM_K + h * 1024 + n * 16 + d]     = v2.x + bb.x;
                smem[SM_K + h * 1024 + n * 16 + d + 1] = v2.y + bb.y;
            }
        } else {
            const int c = co0 - 256, h = c >> 4, d = c & 15;
            const float s0 = g_aff[bat * 256 + c];
            const float b0 = g_aff[bat * 256 + 128 + c];
            const float s1 = g_aff[bat * 256 + c + 1];
            const float b1 = g_aff[bat * 256 + 128 + c + 1];
#pragma unroll
            for (int ri = 0; ri < 4; ri++) {
                const int n = ty + 16 * ri;
                float2 v2 = unpack2(acc[ri][ci]);
                smem[SM_V + h * 1024 + n * 16 + d]     = fmaf(s0, v2.x + bb.x, b0);
                smem[SM_V + h * 1024 + n * 16 + d + 1] = fmaf(s1, v2.y + bb.y, b1);
            }
        }
    }
    __syncthreads();

    // ---- phase 2: attention (one (h,n) row per thread, twice) -----------
    for (int t = 0; t < 2; t++) {
        const int task = tid + t * 256;
        const int h = task >> 6, n = task & 63;
        const u64* q2p = (const u64*)(smem + SM_Q + h * 1024 + n * 16);
        u64 q2[8];
#pragma unroll
        for (int i = 0; i < 8; i++) q2[i] = q2p[i];

        const float* rpbr = g_rpb + h * 4096 + n * 64;
        const float* mr   = mask + (size_t)w * 4096 + n * 64;
        float s[64];
        // prefetch bias+mask first (high MLP)
#pragma unroll
        for (int m = 0; m < 64; m++) s[m] = rpbr[m] + mr[m];

        float mx = -1e30f;
#pragma unroll
        for (int m = 0; m < 64; m++) {
            const u64* k2 = (const u64*)(smem + SM_K + h * 1024 + m * 16);
            u64 a2 = 0ULL;
#pragma unroll
            for (int i = 0; i < 8; i++) ffma2(a2, q2[i], k2[i]);
            float2 r = unpack2(a2);
            s[m] += r.x + r.y;
            mx = fmaxf(mx, s[m]);
        }
        float sum = 0.f;
#pragma unroll
        for (int m = 0; m < 64; m++) {
            float p = __expf(s[m] - mx);
            s[m] = p;
            sum += p;
        }
        const float inv = 1.f / sum;

        u64 o2[8];
#pragma unroll
        for (int i = 0; i < 8; i++) o2[i] = 0ULL;
#pragma unroll
        for (int m = 0; m < 64; m++) {
            u64 p2 = pack2(s[m], s[m]);
            const u64* v2p = (const u64*)(smem + SM_V + h * 1024 + m * 16);
#pragma unroll
            for (int i = 0; i < 8; i++) ffma2(o2[i], p2, v2p[i]);
        }
        float* orow = smem + SM_X + n * DIM + h * 16;   // out[n][h*16+d]
#pragma unroll
        for (int i = 0; i < 8; i++) {
            float2 r = unpack2(o2[i]);
            float2 o; o.x = r.x * inv; o.y = r.y * inv;
            *(float2*)(orow + 2 * i) = o;
        }
    }
    __syncthreads();

    // ---- phase 3: output proj 64x128x128 (proj_w fully staged) ----------
    float* PwT = smem + SM_Q;   // [k][c], stride PSTR (overwrites dead q/k/v)
    for (int i4 = tid; i4 < 128 * 32; i4 += 256) {
        int c = i4 >> 5, k4 = i4 & 31;
        float4 v = *(const float4*)(proj_w + c * DIM + k4 * 4);
        PwT[(k4 * 4 + 0) * PSTR + c] = v.x;
        PwT[(k4 * 4 + 1) * PSTR + c] = v.y;
        PwT[(k4 * 4 + 2) * PSTR + c] = v.z;
        PwT[(k4 * 4 + 3) * PSTR + c] = v.w;
    }
    __syncthreads();

    u64 pacc[4][4];
#pragma unroll
    for (int ri = 0; ri < 4; ri++)
#pragma unroll
        for (int ci = 0; ci < 4; ci++) pacc[ri][ci] = 0ULL;

#pragma unroll 8
    for (int k = 0; k < 128; k++) {
        const float* pr = PwT + k * PSTR + 2 * tx;
        u64 xx[4];
#pragma unroll
        for (int ri = 0; ri < 4; ri++) {
            float xv = smem[SM_X + (ty + 16 * ri) * DIM + k];
            xx[ri] = pack2(xv, xv);
        }
#pragma unroll
        for (int ci = 0; ci < 4; ci++) {
            u64 w2 = *(const u64*)(pr + 32 * ci);
#pragma unroll
            for (int ri = 0; ri < 4; ri++) ffma2(pacc[ri][ci], xx[ri], w2);
        }
    }

    float* og = out + (size_t)bwin * NTOK * DIM;
#pragma unroll
    for (int ci = 0; ci < 4; ci++) {
        const int co0 = 32 * ci + 2 * tx;
        const float2 bb = make_float2(proj_b[co0], proj_b[co0 + 1]);
#pragma unroll
        for (int ri = 0; ri < 4; ri++) {
            const int n = ty + 16 * ri;
            float2 r = unpack2(pacc[ri][ci]);
            float2 o; o.x = r.x + bb.x; o.y = r.y + bb.y;
            *(float2*)(og + n * DIM + co0) = o;
        }
    }
}

// ---------------------------------------------------------------------------
extern "C" void kernel_launch(void* const* d_in, const int* in_sizes, int n_in,
                              void* d_out, int out_size) {
    const float* x          = (const float*)d_in[0];
    const float* mask       = (const float*)d_in[1];
    const float* frame_type = (const float*)d_in[2];
    const float* qkv_w      = (const float*)d_in[3];
    const float* qkv_b      = (const float*)d_in[4];
    const float* table      = (const float*)d_in[5];
    const float* proj_w     = (const float*)d_in[6];
    const float* proj_b     = (const float*)d_in[7];
    const float* aff_w1     = (const float*)d_in[8];
    const float* aff_b1     = (const float*)d_in[9];
    const float* aff_w2     = (const float*)d_in[10];
    const int*   rel_index  = (const int*)d_in[11];
    float* out = (float*)d_out;

    cudaFuncSetAttribute(win_attn_kernel,
                         cudaFuncAttributeMaxDynamicSharedMemorySize, SMEM_BYTES);

    prep_kernel<<<129, 256>>>(frame_type, table, aff_w1, aff_b1, aff_w2, rel_index);
    win_attn_kernel<<<NWIN, 256, SMEM_BYTES>>>(x, mask, qkv_w, qkv_b,
                                               proj_w, proj_b, out);
}

// round 3
// speedup vs baseline: 1.2918x; 1.2918x over previous
#include <cuda_runtime.h>

// ---------------------------------------------------------------------------
// WindowAttention fused kernel, head-split 2 CTAs/window, occ=2, sm_103a
//   B_=2048 windows, N=64 tokens, DIM=128, H=8, HD=16
// ---------------------------------------------------------------------------

#define NWIN   2048
#define NTOK   64
#define DIM    128
#define NHEAD  8
#define HD     16
#define ATT_SCALE 0.25f   // 16^-0.5

typedef unsigned long long u64;

// device scratch (no cudaMalloc allowed)
__device__ float g_rpb[NHEAD * NTOK * NTOK];   // [h][n][m]
__device__ float g_aff[512];                   // [b][scale(128)|bias(128)]

// ---- packed f32x2 helpers -------------------------------------------------
__device__ __forceinline__ u64 pack2(float lo, float hi) {
    u64 r; asm("mov.b64 %0, {%1,%2};" : "=l"(r) : "f"(lo), "f"(hi)); return r;
}
__device__ __forceinline__ float2 unpack2(u64 v) {
    float2 f; asm("mov.b64 {%0,%1}, %2;" : "=f"(f.x), "=f"(f.y) : "l"(v)); return f;
}
__device__ __forceinline__ void ffma2(u64& d, u64 a, u64 b) {
    asm("fma.rn.f32x2 %0, %1, %2, %3;" : "=l"(d) : "l"(a), "l"(b), "l"(d));
}

// ---- prep: rel-pos-bias gather + affine MLP -------------------------------
__global__ void prep_kernel(const float* __restrict__ frame_type,
                            const float* __restrict__ table,
                            const float* __restrict__ aff_w1,
                            const float* __restrict__ aff_b1,
                            const float* __restrict__ aff_w2,
                            const int*   __restrict__ rel_index) {
    int tid = threadIdx.x;
    int blk = blockIdx.x;
    if (blk < 128) {
        int idx = blk * 256 + tid;               // < 32768
        int h  = idx >> 12;
        int nm = idx & 4095;
        g_rpb[idx] = table[rel_index[nm] * NHEAD + h];
    } else {
        int c = tid;                             // 0..255
        for (int b = 0; b < 2; b++) {
            float hdn[16];
#pragma unroll
            for (int j = 0; j < 16; j++) {
                float a = aff_b1[j];
                a = fmaf(frame_type[b * 2 + 0], aff_w1[j * 2 + 0], a);
                a = fmaf(frame_type[b * 2 + 1], aff_w1[j * 2 + 1], a);
                hdn[j] = 1.f / (1.f + __expf(-a));
            }
            float ap = 0.f;
#pragma unroll
            for (int j = 0; j < 16; j++) ap = fmaf(hdn[j], aff_w2[c * 16 + j], ap);
            if (c < 128) {
                g_aff[b * 256 + c] = fmaxf(ap, 0.f) + log1pf(__expf(-fabsf(ap)));
            } else {
                g_aff[b * 256 + c] = ap;         // bias as-is
            }
        }
    }
}

// ---- SMEM layout (floats) -------------------------------------------------
// X:    [64][128]              8192  @ 0
// Q/K/V: per-CTA 4 heads, head stride 1032 (pad -> conflict-free STS)
#define SM_X   0
#define SM_Q   8192
#define HSTR   1032                 // head stride in floats (4128B, 16B-aligned)
#define QREG   (4 * HSTR)           // 4128 floats per q/k/v region
#define SM_K   (SM_Q + QREG)        // 12320
#define SM_V   (SM_K + QREG)        // 16448
#define SM_W   (SM_V + QREG)        // 20576: W chunk (16x196) / aout (64x66)
#define W2STR  196
#define ASTR   66                   // aout row stride (floats)
#define SMEM_FLOATS (SM_W + NTOK * ASTR)   // 24800
#define SMEM_BYTES  (SMEM_FLOATS * 4)      // 99200
#define PSTR   132                  // proj PwT stride (at SM_Q, 64x132=8448)

// ---- main fused kernel ----------------------------------------------------
__global__ __launch_bounds__(256, 2)
void win_attn_kernel(const float* __restrict__ x,
                     const float* __restrict__ mask,
                     const float* __restrict__ qkv_w,
                     const float* __restrict__ qkv_b,
                     const float* __restrict__ proj_w,
                     const float* __restrict__ proj_b,
                     float* __restrict__ out) {
    extern __shared__ float smem[];
    const int tid  = threadIdx.x;
    const int bwin = blockIdx.x >> 1;   // window
    const int cg   = blockIdx.x & 1;    // head-group (heads 4cg..4cg+3)
    const int bat  = bwin >> 10;        // true batch (0/1)
    const int w    = bwin & 1023;       // window index for mask
    const int tx   = tid & 15;
    const int ty   = tid >> 4;

    // ---- load x tile (64x128) -------------------------------------------
    {
        const float4* xg4 = (const float4*)(x + (size_t)bwin * NTOK * DIM);
        float4* xs4 = (float4*)(smem + SM_X);
        for (int i = tid; i < NTOK * DIM / 4; i += 256) xs4[i] = xg4[i];
    }
    __syncthreads();

    // ---- phase 1: QKV GEMM 64 x 192 x 128 (this CTA's 4 heads) ----------
    // thread tile: 4 rows (ty+16ri) x 6 col-pairs (l = 64g + 4tx + 2p)
    u64 acc[4][3][2];
#pragma unroll
    for (int ri = 0; ri < 4; ri++)
#pragma unroll
        for (int g = 0; g < 3; g++) { acc[ri][g][0] = 0ULL; acc[ri][g][1] = 0ULL; }

    for (int kc = 0; kc < 8; kc++) {
        const int k0 = kc * 16;
        if (kc) __syncthreads();   // previous chunk fully consumed
        // stage W chunk: WcT[j][l] = qkv_w[G(l)][k0+j], l in [0,192)
#pragma unroll
        for (int it = 0; it < 3; it++) {
            int i4 = tid + it * 256;            // < 768
            int col = i4 >> 2, j4 = i4 & 3;
            int gcol = ((col >> 6) << 7) + 64 * cg + (col & 63);
            float4 v = *(const float4*)(qkv_w + gcol * DIM + k0 + j4 * 4);
            float* dst = smem + SM_W + col;
            dst[(j4 * 4 + 0) * W2STR] = v.x;
            dst[(j4 * 4 + 1) * W2STR] = v.y;
            dst[(j4 * 4 + 2) * W2STR] = v.z;
            dst[(j4 * 4 + 3) * W2STR] = v.w;
        }
        __syncthreads();
#pragma unroll
        for (int j = 0; j < 16; j++) {
            u64 xx[4];
#pragma unroll
            for (int ri = 0; ri < 4; ri++) {
                float xv = smem[SM_X + (ty + 16 * ri) * DIM + k0 + j];
                xx[ri] = pack2(xv, xv);
            }
            const float* wr = smem + SM_W + j * W2STR + 4 * tx;
#pragma unroll
            for (int g = 0; g < 3; g++) {
                ulonglong2 w2 = *(const ulonglong2*)(wr + 64 * g);
#pragma unroll
                for (int ri = 0; ri < 4; ri++) {
                    ffma2(acc[ri][g][0], xx[ri], w2.x);
                    ffma2(acc[ri][g][1], xx[ri], w2.y);
                }
            }
        }
    }

    // ---- writeback q (scaled), k, v (affine) into [hl][n][d] SMEM -------
#pragma unroll
    for (int g = 0; g < 3; g++) {
#pragma unroll
        for (int p = 0; p < 2; p++) {
            const int cs = 4 * tx + 2 * p;            // 0..63 within section
            const int gc = 128 * g + 64 * cg + cs;    // global qkv column
            const float2 bb = make_float2(qkv_b[gc], qkv_b[gc + 1]);
            const int hl = cs >> 4, d = cs & 15;
            float* base = smem + SM_Q + g * QREG + hl * HSTR + d;
            if (g == 0) {
#pragma unroll
                for (int ri = 0; ri < 4; ri++) {
                    const int n = ty + 16 * ri;
                    float2 v2 = unpack2(acc[ri][g][p]);
                    float2 o; o.x = (v2.x + bb.x) * ATT_SCALE;
                    o.y = (v2.y + bb.y) * ATT_SCALE;
                    *(float2*)(base + n * 16) = o;
                }
            } else if (g == 1) {
#pragma unroll
                for (int ri = 0; ri < 4; ri++) {
                    const int n = ty + 16 * ri;
                    float2 v2 = unpack2(acc[ri][g][p]);
                    float2 o; o.x = v2.x + bb.x; o.y = v2.y + bb.y;
                    *(float2*)(base + n * 16) = o;
                }
            } else {
                const int c = 64 * cg + cs;           // v channel
                const float s0 = g_aff[bat * 256 + c];
                const float b0 = g_aff[bat * 256 + 128 + c];
                const float s1 = g_aff[bat * 256 + c + 1];
                const float b1 = g_aff[bat * 256 + 128 + c + 1];
#pragma unroll
                for (int ri = 0; ri < 4; ri++) {
                    const int n = ty + 16 * ri;
                    float2 v2 = unpack2(acc[ri][g][p]);
                    float2 o; o.x = fmaf(s0, v2.x + bb.x, b0);
                    o.y = fmaf(s1, v2.y + bb.y, b1);
                    *(float2*)(base + n * 16) = o;
                }
            }
        }
    }
    __syncthreads();

    // ---- phase 2: attention, one (hl, n) row per thread -----------------
    {
        const int hl = tid >> 6, n = tid & 63;
        const int hg = 4 * cg + hl;
        const ulonglong2* q4 = (const ulonglong2*)(smem + SM_Q + hl * HSTR + n * HD);
        u64 q2[8];
        {
            ulonglong2 a = q4[0], b = q4[1], c = q4[2], d = q4[3];
            q2[0] = a.x; q2[1] = a.y; q2[2] = b.x; q2[3] = b.y;
            q2[4] = c.x; q2[5] = c.y; q2[6] = d.x; q2[7] = d.y;
        }
        const float* rpbr = g_rpb + hg * 4096 + n * 64;
        const float* mr   = mask + (size_t)w * 4096 + n * 64;
        float s[64];
#pragma unroll
        for (int m4 = 0; m4 < 16; m4++) {
            float4 a = *(const float4*)(rpbr + 4 * m4);
            float4 b = *(const float4*)(mr + 4 * m4);
            s[4 * m4 + 0] = a.x + b.x;
            s[4 * m4 + 1] = a.y + b.y;
            s[4 * m4 + 2] = a.z + b.z;
            s[4 * m4 + 3] = a.w + b.w;
        }
        const char* kbase = (const char*)(smem + SM_K + hl * HSTR);
        float mx = -1e30f;
#pragma unroll 16
        for (int m = 0; m < 64; m++) {
            const ulonglong2* kp = (const ulonglong2*)(kbase + m * 64);
            ulonglong2 ka = kp[0], kb = kp[1], kc2 = kp[2], kd = kp[3];
            u64 a2 = 0ULL, b2 = 0ULL;
            ffma2(a2, q2[0], ka.x);  ffma2(b2, q2[1], ka.y);
            ffma2(a2, q2[2], kb.x);  ffma2(b2, q2[3], kb.y);
            ffma2(a2, q2[4], kc2.x); ffma2(b2, q2[5], kc2.y);
            ffma2(a2, q2[6], kd.x);  ffma2(b2, q2[7], kd.y);
            float2 ra = unpack2(a2), rb = unpack2(b2);
            s[m] += (ra.x + ra.y) + (rb.x + rb.y);
            mx = fmaxf(mx, s[m]);
        }
        float sum = 0.f;
#pragma unroll
        for (int m = 0; m < 64; m++) {
            float p = __expf(s[m] - mx);
            s[m] = p;
            sum += p;
        }
        const float inv = 1.f / sum;

        u64 o2[8];
#pragma unroll
        for (int i = 0; i < 8; i++) o2[i] = 0ULL;
        const char* vbase = (const char*)(smem + SM_V + hl * HSTR);
#pragma unroll 16
        for (int m = 0; m < 64; m++) {
            const ulonglong2* vp = (const ulonglong2*)(vbase + m * 64);
            ulonglong2 va = vp[0], vb = vp[1], vc = vp[2], vd = vp[3];
            u64 p2 = pack2(s[m], s[m]);
            ffma2(o2[0], p2, va.x); ffma2(o2[1], p2, va.y);
            ffma2(o2[2], p2, vb.x); ffma2(o2[3], p2, vb.y);
            ffma2(o2[4], p2, vc.x); ffma2(o2[5], p2, vc.y);
            ffma2(o2[6], p2, vd.x); ffma2(o2[7], p2, vd.y);
        }
        float* orow = smem + SM_W + n * ASTR + hl * HD;   // aout[n][local 64]
#pragma unroll
        for (int i = 0; i < 8; i++) {
            float2 r = unpack2(o2[i]);
            float2 o; o.x = r.x * inv; o.y = r.y * inv;
            *(float2*)(orow + 2 * i) = o;
        }
    }
    __syncthreads();

    // ---- phase 3: partial proj 64 x 128 x 64 (this CTA's k-half) --------
    // stage PwT[kl][c] (kl local k in [0,64), global k = 64cg + kl)
    {
        float* PwT = smem + SM_Q;   // overwrites dead q/k/v (8448 <= 12384)
#pragma unroll
        for (int it = 0; it < 8; it++) {
            int i4 = tid + it * 256;            // < 2048
            int c = i4 >> 4, k4 = i4 & 15;
            float4 v = *(const float4*)(proj_w + c * DIM + 64 * cg + 4 * k4);
            PwT[(4 * k4 + 0) * PSTR + c] = v.x;
            PwT[(4 * k4 + 1) * PSTR + c] = v.y;
            PwT[(4 * k4 + 2) * PSTR + c] = v.z;
            PwT[(4 * k4 + 3) * PSTR + c] = v.w;
        }
    }
    __syncthreads();

    u64 pacc[4][2][2];
#pragma unroll
    for (int ri = 0; ri < 4; ri++)
#pragma unroll
        for (int g2 = 0; g2 < 2; g2++) { pacc[ri][g2][0] = 0ULL; pacc[ri][g2][1] = 0ULL; }

#pragma unroll 8
    for (int kl = 0; kl < 64; kl++) {
        u64 xx[4];
#pragma unroll
        for (int ri = 0; ri < 4; ri++) {
            float xv = smem[SM_W + (ty + 16 * ri) * ASTR + kl];
            xx[ri] = pack2(xv, xv);
        }
        const float* pr = smem + SM_Q + kl * PSTR + 4 * tx;
#pragma unroll
        for (int g2 = 0; g2 < 2; g2++) {
            ulonglong2 w2 = *(const ulonglong2*)(pr + 64 * g2);
#pragma unroll
            for (int ri = 0; ri < 4; ri++) {
                ffma2(pacc[ri][g2][0], xx[ri], w2.x);
                ffma2(pacc[ri][g2][1], xx[ri], w2.y);
            }
        }
    }

    // accumulate partials into zero-initialized out (2 contributors/elem)
    float* og = out + (size_t)bwin * NTOK * DIM;
#pragma unroll
    for (int g2 = 0; g2 < 2; g2++) {
#pragma unroll
        for (int p = 0; p < 2; p++) {
            const int c0 = 64 * g2 + 4 * tx + 2 * p;
            float2 bb = make_float2(0.f, 0.f);
            if (cg == 0) { bb.x = proj_b[c0]; bb.y = proj_b[c0 + 1]; }
#pragma unroll
            for (int ri = 0; ri < 4; ri++) {
                const int n = ty + 16 * ri;
                float2 r = unpack2(pacc[ri][g2][p]);
                atomicAdd(&og[n * DIM + c0], r.x + bb.x);
                atomicAdd(&og[n * DIM + c0 + 1], r.y + bb.y);
            }
        }
    }
}

// ---------------------------------------------------------------------------
extern "C" void kernel_launch(void* const* d_in, const int* in_sizes, int n_in,
                              void* d_out, int out_size) {
    const float* x          = (const float*)d_in[0];
    const float* mask       = (const float*)d_in[1];
    const float* frame_type = (const float*)d_in[2];
    const float* qkv_w      = (const float*)d_in[3];
    const float* qkv_b      = (const float*)d_in[4];
    const float* table      = (const float*)d_in[5];
    const float* proj_w     = (const float*)d_in[6];
    const float* proj_b     = (const float*)d_in[7];
    const float* aff_w1     = (const float*)d_in[8];
    const float* aff_b1     = (const float*)d_in[9];
    const float* aff_w2     = (const float*)d_in[10];
    const int*   rel_index  = (const int*)d_in[11];
    float* out = (float*)d_out;

    cudaFuncSetAttribute(win_attn_kernel,
                         cudaFuncAttributeMaxDynamicSharedMemorySize, SMEM_BYTES);

    cudaMemsetAsync(out, 0, (size_t)out_size * sizeof(float));
    prep_kernel<<<129, 256>>>(frame_type, table, aff_w1, aff_b1, aff_w2, rel_index);
    win_attn_kernel<<<NWIN * 2, 256, SMEM_BYTES>>>(x, mask, qkv_w, qkv_b,
                                                   proj_w, proj_b, out);
}